// round 6
// baseline (speedup 1.0000x reference)
#include <cuda_runtime.h>
#include <math.h>

// Problem constants
#define NB 16
#define NC 3
#define NT 600
#define HW 5184          // 72*72
#define HW4 (HW/4)       // 1296 float4 per row
#define ROWS (NB*NC*NT)  // 28800

// Scratch: spatial means [b][c][t], and per-batch Gram accumulators.
// g_gram is zero-initialized at module load; project_kernel re-zeroes it
// after consuming, so every graph replay starts from zero.
__device__ float g_x[ROWS];
__device__ float g_gram[NB][8];

// ---------------------------------------------------------------------------
// Kernel 1: one block per (b,t). Streams all 3 channel rows (3 x 20.7 KB),
// computes 3 spatial means, writes them to g_x, and accumulates the 6
// Gram outer-product terms into g_gram[b] via global atomics — all hidden
// under the HBM streaming time.
// ---------------------------------------------------------------------------
__global__ __launch_bounds__(256) void mean_gram_kernel(const float* __restrict__ in,
                                                        float* __restrict__ xout) {
    const int bt = blockIdx.x;
    const int b = bt / NT;
    const int t = bt - b * NT;

    const float4* base = reinterpret_cast<const float4*>(in);
    const size_t row0 = ((size_t)b * NC * NT + t) * HW4;      // c = 0
    const size_t cstride = (size_t)NT * HW4;

    const float4* __restrict__ p0 = base + row0;
    const float4* __restrict__ p1 = base + row0 + cstride;
    const float4* __restrict__ p2 = base + row0 + 2 * cstride;

    float s0 = 0.0f, s1 = 0.0f, s2 = 0.0f;
    for (int i = threadIdx.x; i < HW4; i += 256) {
        float4 v0 = __ldg(&p0[i]);
        float4 v1 = __ldg(&p1[i]);
        float4 v2 = __ldg(&p2[i]);
        s0 += (v0.x + v0.y) + (v0.z + v0.w);
        s1 += (v1.x + v1.y) + (v1.z + v1.w);
        s2 += (v2.x + v2.y) + (v2.z + v2.w);
    }

    #pragma unroll
    for (int o = 16; o > 0; o >>= 1) {
        s0 += __shfl_down_sync(0xffffffffu, s0, o);
        s1 += __shfl_down_sync(0xffffffffu, s1, o);
        s2 += __shfl_down_sync(0xffffffffu, s2, o);
    }

    __shared__ float ws[8][3];
    const int lane = threadIdx.x & 31;
    const int warp = threadIdx.x >> 5;
    if (lane == 0) { ws[warp][0] = s0; ws[warp][1] = s1; ws[warp][2] = s2; }
    __syncthreads();

    if (threadIdx.x == 0) {
        float m0 = 0.0f, m1 = 0.0f, m2 = 0.0f;
        #pragma unroll
        for (int w = 0; w < 8; ++w) { m0 += ws[w][0]; m1 += ws[w][1]; m2 += ws[w][2]; }
        const float inv = 1.0f / (float)HW;
        m0 *= inv; m1 *= inv; m2 *= inv;

        xout[(b * NC + 0) * NT + t] = m0;
        xout[(b * NC + 1) * NT + t] = m1;
        xout[(b * NC + 2) * NT + t] = m2;

        atomicAdd(&g_gram[b][0], m0 * m0);
        atomicAdd(&g_gram[b][1], m0 * m1);
        atomicAdd(&g_gram[b][2], m0 * m2);
        atomicAdd(&g_gram[b][3], m1 * m1);
        atomicAdd(&g_gram[b][4], m1 * m2);
        atomicAdd(&g_gram[b][5], m2 * m2);
    }
}

// ---------------------------------------------------------------------------
// Kernel 2: one block per batch. Gram is already reduced. ALL threads run the
// eigensolve redundantly (no serialize-then-broadcast), then project and emit
// the green channel. Re-zeroes g_gram[b] at the end for the next replay.
// ---------------------------------------------------------------------------
__global__ __launch_bounds__(256) void project_kernel(const float* __restrict__ x,
                                                      float* __restrict__ out) {
    const int b = blockIdx.x;
    const float* x0 = x + (size_t)b * NC * NT;
    const float* x1 = x0 + NT;
    const float* x2 = x0 + 2 * NT;

    const float f00 = g_gram[b][0], f01 = g_gram[b][1], f02 = g_gram[b][2];
    const float f11 = g_gram[b][3], f12 = g_gram[b][4], f22 = g_gram[b][5];

    // ---- Stage 1 (all float): trig dominant eigenvalue + eigenvector ----
    float p1 = f01 * f01 + f02 * f02 + f12 * f12;
    float q = (f00 + f11 + f22) * (1.0f / 3.0f);
    float d0 = f00 - q, d1 = f11 - q, d2 = f22 - q;
    float p2 = d0 * d0 + d1 * d1 + d2 * d2 + 2.0f * p1;
    float pf = sqrtf(p2 * (1.0f / 6.0f));
    float lam_f = q;
    if (pf > 0.0f) {
        float ip = 1.0f / pf;
        float b00 = d0 * ip, b11 = d1 * ip, b22 = d2 * ip;
        float b01 = f01 * ip, b02 = f02 * ip, b12 = f12 * ip;
        float detB = b00 * (b11 * b22 - b12 * b12)
                   - b01 * (b01 * b22 - b12 * b02)
                   + b02 * (b01 * b12 - b11 * b02);
        float r = fminf(1.0f, fmaxf(-1.0f, 0.5f * detB));
        lam_f = q + 2.0f * pf * cosf(acosf(r) * (1.0f / 3.0f));
    }

    // Float cross-product eigenvector candidate
    float g0x = f00 - lam_f, g0y = f01,         g0z = f02;
    float g1x = f01,         g1y = f11 - lam_f, g1z = f12;
    float g2x = f02,         g2y = f12,         g2z = f22 - lam_f;

    float e0x = g0y * g1z - g0z * g1y, e0y = g0z * g1x - g0x * g1z, e0z = g0x * g1y - g0y * g1x;
    float e1x = g1y * g2z - g1z * g2y, e1y = g1z * g2x - g1x * g2z, e1z = g1x * g2y - g1y * g2x;
    float e2x = g2y * g0z - g2z * g0y, e2y = g2z * g0x - g2x * g0z, e2z = g2x * g0y - g2y * g0x;

    float q0 = e0x * e0x + e0y * e0y + e0z * e0z;
    float q1 = e1x * e1x + e1y * e1y + e1z * e1z;
    float q2 = e2x * e2x + e2y * e2y + e2z * e2z;

    float fvx, fvy, fvz, fnn;
    if (q0 >= q1 && q0 >= q2) { fvx = e0x; fvy = e0y; fvz = e0z; fnn = q0; }
    else if (q1 >= q2)        { fvx = e1x; fvy = e1y; fvz = e1z; fnn = q1; }
    else                      { fvx = e2x; fvy = e2y; fvz = e2z; fnn = q2; }

    const float trf = f00 + f11 + f22;
    if (!(fnn > 1e-16f * trf * trf * trf * trf)) {
        // Degenerate: short float power iteration (rare path)
        fvx = 0.5773503f; fvy = 0.5773503f; fvz = 0.5773503f;
        for (int it = 0; it < 48; ++it) {
            float tx = f00 * fvx + f01 * fvy + f02 * fvz;
            float ty = f01 * fvx + f11 * fvy + f12 * fvz;
            float tz = f02 * fvx + f12 * fvy + f22 * fvz;
            float inv = rsqrtf(tx * tx + ty * ty + tz * tz + 1e-30f);
            fvx = tx * inv; fvy = ty * inv; fvz = tz * inv;
        }
    } else {
        float inv = rsqrtf(fnn);
        fvx *= inv; fvy *= inv; fvz *= inv;
    }

    // ---- Stage 2 (single double pass): Rayleigh + cross-product ----
    const double a00 = (double)f00, a01 = (double)f01, a02 = (double)f02;
    const double a11 = (double)f11, a12 = (double)f12, a22 = (double)f22;
    double vx = (double)fvx, vy = (double)fvy, vz = (double)fvz;

    double tx = a00 * vx + a01 * vy + a02 * vz;
    double ty = a01 * vx + a11 * vy + a12 * vz;
    double tz = a02 * vx + a12 * vy + a22 * vz;
    double vv = vx * vx + vy * vy + vz * vz;
    // reciprocal of vv: float seed + one double Newton step (no fp64 div)
    double rvv = (double)(1.0f / (float)vv);
    rvv = rvv * (2.0 - vv * rvv);
    double lam = (vx * tx + vy * ty + vz * tz) * rvv;

    double r0x = a00 - lam, r0y = a01,       r0z = a02;
    double r1x = a01,       r1y = a11 - lam, r1z = a12;
    double r2x = a02,       r2y = a12,       r2z = a22 - lam;

    double c0x = r0y * r1z - r0z * r1y, c0y = r0z * r1x - r0x * r1z, c0z = r0x * r1y - r0y * r1x;
    double c1x = r1y * r2z - r1z * r2y, c1y = r1z * r2x - r1x * r2z, c1z = r1x * r2y - r1y * r2x;
    double c2x = r2y * r0z - r2z * r0y, c2y = r2z * r0x - r2x * r0z, c2z = r2x * r0y - r2y * r0x;

    double n0 = c0x * c0x + c0y * c0y + c0z * c0z;
    double n1 = c1x * c1x + c1y * c1y + c1z * c1z;
    double n2 = c2x * c2x + c2y * c2y + c2z * c2z;

    double wx, wy, wz, nn;
    if (n0 >= n1 && n0 >= n2) { wx = c0x; wy = c0y; wz = c0z; nn = n0; }
    else if (n1 >= n2)        { wx = c1x; wy = c1y; wz = c1z; nn = n1; }
    else                      { wx = c2x; wy = c2y; wz = c2z; nn = n2; }

    float s0f, s1f, s2f;
    if (nn > 0.0) {
        float invf = rsqrtf((float)nn);
        double inv = (double)invf;
        inv = inv * (1.5 - 0.5 * nn * inv * inv);
        s0f = (float)(wx * inv); s1f = (float)(wy * inv); s2f = (float)(wz * inv);
    } else {
        s0f = fvx; s1f = fvy; s2f = fvz;
    }

    // ---- Projection: out[b][n] = x1[n] - s1 * (s . x[:,n]) ----
    for (int n = threadIdx.x; n < NT; n += blockDim.x) {
        float a = x0[n], c = x1[n], d = x2[n];
        float dot = s0f * a + s1f * c + s2f * d;
        out[(size_t)b * NT + n] = c - s1f * dot;
    }

    // Re-zero this batch's gram accumulators for the next graph replay.
    // __syncthreads ensures every thread has finished READING g_gram[b]
    // before any thread overwrites it.
    __syncthreads();
    if (threadIdx.x < 6) g_gram[b][threadIdx.x] = 0.0f;
}

extern "C" void kernel_launch(void* const* d_in, const int* in_sizes, int n_in,
                              void* d_out, int out_size) {
    const float* batch_x = (const float*)d_in[0];
    float* out = (float*)d_out;

    float* xbuf;
    cudaGetSymbolAddress((void**)&xbuf, g_x);

    mean_gram_kernel<<<NB * NT, 256>>>(batch_x, xbuf);
    project_kernel<<<NB, 256>>>(xbuf, out);
}

// round 8
// speedup vs baseline: 1.1154x; 1.1154x over previous
#include <cuda_runtime.h>
#include <math.h>

// Problem constants
#define NB 16
#define NC 3
#define NT 600
#define HW 5184          // 72*72
#define HW4 (HW/4)       // 1296 float4 per row
#define ROWS (NB*NC*NT)  // 28800

// Scratch: spatial means, layout [b][c][t]
__device__ float g_x[ROWS];

// ---------------------------------------------------------------------------
// Kernel 1: mean over H*W for each (b,c,t) row. One block per row.
// Pure HBM streaming; 2-way unrolled. Measured ~88us (~7.1 TB/s).
// ---------------------------------------------------------------------------
__global__ __launch_bounds__(256) void mean_kernel(const float* __restrict__ in,
                                                   float* __restrict__ xout) {
    const int row = blockIdx.x;
    const float4* p = reinterpret_cast<const float4*>(in) + (size_t)row * HW4;

    float s0 = 0.0f, s1 = 0.0f;
    int i = threadIdx.x;
    for (; i + 256 < HW4; i += 512) {
        float4 v0 = __ldg(&p[i]);
        float4 v1 = __ldg(&p[i + 256]);
        s0 += (v0.x + v0.y) + (v0.z + v0.w);
        s1 += (v1.x + v1.y) + (v1.z + v1.w);
    }
    if (i < HW4) {
        float4 v = __ldg(&p[i]);
        s0 += (v.x + v.y) + (v.z + v.w);
    }
    float s = s0 + s1;

    #pragma unroll
    for (int o = 16; o > 0; o >>= 1) s += __shfl_down_sync(0xffffffffu, s, o);

    __shared__ float ws[8];
    const int lane = threadIdx.x & 31;
    const int warp = threadIdx.x >> 5;
    if (lane == 0) ws[warp] = s;
    __syncthreads();
    if (warp == 0) {
        s = (lane < 8) ? ws[lane] : 0.0f;
        #pragma unroll
        for (int o = 4; o > 0; o >>= 1) s += __shfl_down_sync(0xffffffffu, s, o);
        if (lane == 0) xout[row] = s * (1.0f / (float)HW);
    }
}

// ---------------------------------------------------------------------------
// Kernel 2: per batch — float Gram reduce, thread-0 ALL-FLOAT eigensolve
// (trig + cross-product + one Rayleigh refinement pass; FFMA lat 4, no fp64),
// projection. One block per batch element.
// ---------------------------------------------------------------------------
__global__ __launch_bounds__(256) void project_kernel(const float* __restrict__ x,
                                                      float* __restrict__ out) {
    const int b = blockIdx.x;
    const float* x0 = x + (size_t)b * NC * NT;
    const float* x1 = x0 + NT;
    const float* x2 = x0 + 2 * NT;

    __shared__ float gm[6];
    __shared__ float sv[3];
    if (threadIdx.x < 6) gm[threadIdx.x] = 0.0f;
    __syncthreads();

    float m00 = 0, m01 = 0, m02 = 0, m11 = 0, m12 = 0, m22 = 0;
    for (int n = threadIdx.x; n < NT; n += blockDim.x) {
        float a = x0[n], c = x1[n], d = x2[n];
        m00 = fmaf(a, a, m00); m01 = fmaf(a, c, m01); m02 = fmaf(a, d, m02);
        m11 = fmaf(c, c, m11); m12 = fmaf(c, d, m12); m22 = fmaf(d, d, m22);
    }
    #pragma unroll
    for (int o = 16; o > 0; o >>= 1) {
        m00 += __shfl_down_sync(0xffffffffu, m00, o);
        m01 += __shfl_down_sync(0xffffffffu, m01, o);
        m02 += __shfl_down_sync(0xffffffffu, m02, o);
        m11 += __shfl_down_sync(0xffffffffu, m11, o);
        m12 += __shfl_down_sync(0xffffffffu, m12, o);
        m22 += __shfl_down_sync(0xffffffffu, m22, o);
    }
    if ((threadIdx.x & 31) == 0) {
        atomicAdd(&gm[0], m00); atomicAdd(&gm[1], m01); atomicAdd(&gm[2], m02);
        atomicAdd(&gm[3], m11); atomicAdd(&gm[4], m12); atomicAdd(&gm[5], m22);
    }
    __syncthreads();

    if (threadIdx.x == 0) {
        const float f00 = gm[0], f01 = gm[1], f02 = gm[2];
        const float f11 = gm[3], f12 = gm[4], f22 = gm[5];

        // ---- Trig dominant eigenvalue (float; __cosf hits MUFU) ----
        float p1 = f01 * f01 + f02 * f02 + f12 * f12;
        float q = (f00 + f11 + f22) * (1.0f / 3.0f);
        float d0 = f00 - q, d1 = f11 - q, d2 = f22 - q;
        float p2 = d0 * d0 + d1 * d1 + d2 * d2 + 2.0f * p1;
        float pf = sqrtf(p2 * (1.0f / 6.0f));
        float lam = q;
        if (pf > 0.0f) {
            float ip = __fdividef(1.0f, pf);
            float b00 = d0 * ip, b11 = d1 * ip, b22 = d2 * ip;
            float b01 = f01 * ip, b02 = f02 * ip, b12 = f12 * ip;
            float detB = b00 * (b11 * b22 - b12 * b12)
                       - b01 * (b01 * b22 - b12 * b02)
                       + b02 * (b01 * b12 - b11 * b02);
            float r = fminf(1.0f, fmaxf(-1.0f, 0.5f * detB));
            lam = q + 2.0f * pf * __cosf(acosf(r) * (1.0f / 3.0f));
        }

        // ---- Two passes: cross-product eigenvector, Rayleigh-refined lam ----
        float vx = 0.5773503f, vy = 0.5773503f, vz = 0.5773503f;
        const float trf = f00 + f11 + f22;
        bool ok = false;

        #pragma unroll
        for (int pass = 0; pass < 2; ++pass) {
            float g0x = f00 - lam, g0y = f01,       g0z = f02;
            float g1x = f01,       g1y = f11 - lam, g1z = f12;
            float g2x = f02,       g2y = f12,       g2z = f22 - lam;

            float e0x = g0y * g1z - g0z * g1y, e0y = g0z * g1x - g0x * g1z, e0z = g0x * g1y - g0y * g1x;
            float e1x = g1y * g2z - g1z * g2y, e1y = g1z * g2x - g1x * g2z, e1z = g1x * g2y - g1y * g2x;
            float e2x = g2y * g0z - g2z * g0y, e2y = g2z * g0x - g2x * g0z, e2z = g2x * g0y - g2y * g0x;

            float q0 = e0x * e0x + e0y * e0y + e0z * e0z;
            float q1 = e1x * e1x + e1y * e1y + e1z * e1z;
            float q2 = e2x * e2x + e2y * e2y + e2z * e2z;

            float wx, wy, wz, nn;
            if (q0 >= q1 && q0 >= q2) { wx = e0x; wy = e0y; wz = e0z; nn = q0; }
            else if (q1 >= q2)        { wx = e1x; wy = e1y; wz = e1z; nn = q1; }
            else                      { wx = e2x; wy = e2y; wz = e2z; nn = q2; }

            if (!(nn > 1e-16f * trf * trf * trf * trf)) break;
            ok = true;

            float inv = rsqrtf(nn);
            vx = wx * inv; vy = wy * inv; vz = wz * inv;

            if (pass == 0) {
                // Rayleigh quotient on unit v: refined eigenvalue for pass 2
                float tx = f00 * vx + f01 * vy + f02 * vz;
                float ty = f01 * vx + f11 * vy + f12 * vz;
                float tz = f02 * vx + f12 * vy + f22 * vz;
                lam = vx * tx + vy * ty + vz * tz;
            }
        }

        if (!ok) {
            // Degenerate fallback: float power iteration (rare path)
            vx = 0.5773503f; vy = 0.5773503f; vz = 0.5773503f;
            for (int it = 0; it < 48; ++it) {
                float tx = f00 * vx + f01 * vy + f02 * vz;
                float ty = f01 * vx + f11 * vy + f12 * vz;
                float tz = f02 * vx + f12 * vy + f22 * vz;
                float inv = rsqrtf(tx * tx + ty * ty + tz * tz + 1e-30f);
                vx = tx * inv; vy = ty * inv; vz = tz * inv;
            }
        }
        sv[0] = vx; sv[1] = vy; sv[2] = vz;
    }
    __syncthreads();

    const float s0 = sv[0], s1 = sv[1], s2 = sv[2];
    for (int n = threadIdx.x; n < NT; n += blockDim.x) {
        float a = x0[n], c = x1[n], d = x2[n];
        float dot = s0 * a + s1 * c + s2 * d;
        out[(size_t)b * NT + n] = c - s1 * dot;
    }
}

extern "C" void kernel_launch(void* const* d_in, const int* in_sizes, int n_in,
                              void* d_out, int out_size) {
    const float* batch_x = (const float*)d_in[0];
    float* out = (float*)d_out;

    float* xbuf;
    cudaGetSymbolAddress((void**)&xbuf, g_x);

    mean_kernel<<<ROWS, 256>>>(batch_x, xbuf);
    project_kernel<<<NB, 256>>>(xbuf, out);
}